// round 11
// baseline (speedup 1.0000x reference)
#include <cuda_runtime.h>
#include <cuda_bf16.h>
#include <math.h>

// Problem constants
#define BATCH   8
#define SEQ     8192
#define DMODEL  256
#define NC      512          // chunks along T
#define CHUNK   (SEQ / NC)   // 16  (== scan base block -> one E1 per chunk)
#define NBSPL   2            // batch splits across gridDim.y
#define BPB     (BATCH / NBSPL)  // 4 batches per block

// Scratch (__device__ globals; no cudaMalloc allowed):
// g_P : raw chunk-local complex sums; g_Hin: exclusive chunk prefix. 16.8 MB ea.
// Layout [(b*NC + c)*DMODEL + d] as float4 = (s0r, s0i, s1r, s1i).
__device__ float4 g_P  [BATCH * NC * DMODEL];
__device__ float4 g_Hin[BATCH * NC * DMODEL];

// ---------------------------------------------------------------------------
// Bit-exact emulation of XLA ReduceWindowRewriter's blocked-rescan cumsum of a
// CONSTANT c (base_length = 16), vectorized over 4 lanes
// (phase0, phase1, mag0, mag1). DO NOT TOUCH — this is the bit-critical part.
// ---------------------------------------------------------------------------
__device__ __forceinline__ float4 f4add(float4 a, float4 b) {
    return make_float4(a.x + b.x, a.y + b.y, a.z + b.z, a.w + b.w);
}

__device__ __forceinline__ float4 seqm(float4 v, int m) {   // m >= 1
    float4 a = v;
    for (int k = 1; k < m; k++) a = f4add(a, v);
    return a;
}

__device__ __forceinline__ float4 computeE1(int q, float4 T1, float4 T2, float4 T3) {
    // inclusive scan of constant T1 at q terms (1 <= q <= 511)
    int j  = q - 1, r1 = j & 15, q1 = j >> 4;        // q1 in [0,31]
    float4 in1 = seqm(T1, r1 + 1);
    if (q1 == 0) return in1;
    int j2 = q1 - 1, r2 = j2 & 15, q2 = j2 >> 4;     // q2 in {0,1}
    float4 in2 = seqm(T2, r2 + 1);
    float4 E2  = q2 ? f4add(T3, in2) : in2;
    return f4add(E2, in1);
}

// ---------------------------------------------------------------------------
// Branch-free sin/cos for x in [0, ~7e4): 3-term FMA Cody-Waite reduction
// mod pi/2, MUFU sin/cos on the reduced arg, quadrant fixup via selects.
// Function-VALUE error ~5e-7 abs — only the argument is bit-critical, and the
// argument is the exact fp32 cumsum value.
// ---------------------------------------------------------------------------
__device__ __forceinline__ void fast_sincos(float x, float& s, float& c) {
    float kf = rintf(x * 0.636619772f);          // x * 2/pi
    int   q  = (int)kf;
    float r  = fmaf(kf, -1.57079601e+00f, x);
    r        = fmaf(kf, -3.13916474e-07f, r);
    r        = fmaf(kf, -5.39030253e-15f, r);
    float sr = __sinf(r);
    float cr = __cosf(r);
    bool sw  = (q & 1);
    float ss = sw ? cr : sr;
    float cc = sw ? sr : cr;
    s = (q & 2)       ? -ss : ss;
    c = ((q + 1) & 2) ? -cc : cc;
}

// descale + rescale factors from the exact cum values
struct Fac { float dnr0, dni0, dnr1, dni1, ecr0, eci0, ecr1, eci1; };

__device__ __forceinline__ Fac factors_from_cum(float4 cum) {
    float sn0, cs0, sn1, cs1;
    fast_sincos(cum.x, sn0, cs0);
    fast_sincos(cum.y, sn1, cs1);
    float en0 = __expf(-cum.z), ec0 = __expf(cum.z);
    float en1 = __expf(-cum.w), ec1 = __expf(cum.w);
    Fac f;
    f.dnr0 = en0 * cs0;  f.dni0 = -en0 * sn0;
    f.dnr1 = en1 * cs1;  f.dni1 = -en1 * sn1;
    f.ecr0 = ec0 * cs0;  f.eci0 = ec0 * sn0;
    f.ecr1 = ec1 * cs1;  f.eci1 = ec1 * sn1;
    return f;
}

// descale-only variant for K1
__device__ __forceinline__ float4 descale_from_cum(float4 cum) {
    float sn0, cs0, sn1, cs1;
    fast_sincos(cum.x, sn0, cs0);
    fast_sincos(cum.y, sn1, cs1);
    float en0 = __expf(-cum.z);
    float en1 = __expf(-cum.w);
    return make_float4(en0 * cs0, -en0 * sn0, en1 * cs1, -en1 * sn1);
}

// ---------------------------------------------------------------------------
// K1: chunk-local raw sums S = sum_t descale_t (.) (B * x_t).
// grid = (NC, NBSPL), block = DMODEL. BPB=4 batches/block: low reg pressure.
// ---------------------------------------------------------------------------
__global__ __launch_bounds__(DMODEL, 3) void k_partial(
    const float* __restrict__ x,
    const float* __restrict__ aph, const float* __restrict__ lam,
    const float* __restrict__ Br,  const float* __restrict__ Bi)
{
    const int d  = threadIdx.x;
    const int c  = blockIdx.x;
    const int b0 = blockIdx.y * BPB;

    const float4 cv = make_float4(aph[2 * d + 0], aph[2 * d + 1],
                                  lam[2 * d + 0], lam[2 * d + 1]);
    const float4 T1 = seqm(cv, 16);
    const float4 T2 = seqm(T1, 16);
    const float4 T3 = seqm(T2, 16);

    const float br0 = Br[2 * d + 0], br1 = Br[2 * d + 1];
    const float bi0 = Bi[2 * d + 0], bi1 = Bi[2 * d + 1];

    float S[BPB][4];
    #pragma unroll
    for (int b = 0; b < BPB; b++)
        S[b][0] = S[b][1] = S[b][2] = S[b][3] = 0.f;

    const float* xbase = x + ((size_t)b0 * SEQ + (size_t)c * CHUNK) * DMODEL + d;

    // exactly one 16-step scan block per chunk (q0 == c)
    float4 E1 = make_float4(0.f, 0.f, 0.f, 0.f);
    if (c > 0) E1 = computeE1(c, T1, T2, T3);
    float4 in0 = cv;

    #pragma unroll
    for (int r0 = 0; r0 < CHUNK; r0++) {
        if (r0 > 0) in0 = f4add(in0, cv);

        float xv[BPB];
        #pragma unroll
        for (int b = 0; b < BPB; b++)
            xv[b] = __ldg(xbase + ((size_t)b * SEQ + r0) * DMODEL);

        float4 cum = (c == 0) ? in0 : f4add(E1, in0);
        float4 dn  = descale_from_cum(cum);

        #pragma unroll
        for (int b = 0; b < BPB; b++) {
            float bur0 = br0 * xv[b], bui0 = bi0 * xv[b];
            float bur1 = br1 * xv[b], bui1 = bi1 * xv[b];
            S[b][0] = fmaf(dn.x, bur0, fmaf(-dn.y, bui0, S[b][0]));
            S[b][1] = fmaf(dn.x, bui0, fmaf( dn.y, bur0, S[b][1]));
            S[b][2] = fmaf(dn.z, bur1, fmaf(-dn.w, bui1, S[b][2]));
            S[b][3] = fmaf(dn.z, bui1, fmaf( dn.w, bur1, S[b][3]));
        }
    }

    #pragma unroll
    for (int b = 0; b < BPB; b++)
        g_P[((size_t)(b0 + b) * NC + c) * DMODEL + d] =
            make_float4(S[b][0], S[b][1], S[b][2], S[b][3]);
}

// ---------------------------------------------------------------------------
// K2: exclusive prefix SUM over chunks (plain addition — sums are raw).
// 2048 threads; NC=512 iterations over L2-resident data (unroll for MLP).
// __ldcs: g_P is read-once — evict-first, keep L2 for x (K3 re-reads it).
// ---------------------------------------------------------------------------
__global__ void k_scan() {
    int idx = blockIdx.x * blockDim.x + threadIdx.x;
    if (idx >= BATCH * DMODEL) return;
    int b = idx >> 8;
    int d = idx & (DMODEL - 1);

    float4 s = make_float4(0.f, 0.f, 0.f, 0.f);
    #pragma unroll 16
    for (int c = 0; c < NC; c++) {
        size_t k = ((size_t)b * NC + c) * DMODEL + d;
        g_Hin[k] = s;
        float4 p = __ldcs(&g_P[k]);
        s.x += p.x; s.y += p.y; s.z += p.z; s.w += p.w;
    }
}

// ---------------------------------------------------------------------------
// K3: redo local sums seeded with carry, rescale to h, emit y.
// grid = (NC, NBSPL), BPB=4 -> fits in 85 regs, no spills.
// ---------------------------------------------------------------------------
__global__ __launch_bounds__(DMODEL, 3) void k_output(
    const float* __restrict__ x,
    const float* __restrict__ aph, const float* __restrict__ lam,
    const float* __restrict__ Br,  const float* __restrict__ Bi,
    const float* __restrict__ Cr,  const float* __restrict__ Ci,
    const float* __restrict__ Dd,
    float* __restrict__ y)
{
    const int d  = threadIdx.x;
    const int c  = blockIdx.x;
    const int b0 = blockIdx.y * BPB;

    const float4 cv = make_float4(aph[2 * d + 0], aph[2 * d + 1],
                                  lam[2 * d + 0], lam[2 * d + 1]);
    const float4 T1 = seqm(cv, 16);
    const float4 T2 = seqm(T1, 16);
    const float4 T3 = seqm(T2, 16);

    const float br0 = Br[2 * d + 0], br1 = Br[2 * d + 1];
    const float bi0 = Bi[2 * d + 0], bi1 = Bi[2 * d + 1];
    const float cr0 = Cr[2 * d + 0], cr1 = Cr[2 * d + 1];
    const float ci0 = Ci[2 * d + 0], ci1 = Ci[2 * d + 1];
    const float dd  = Dd[d];

    float S[BPB][4];
    #pragma unroll
    for (int b = 0; b < BPB; b++) {
        float4 h = g_Hin[((size_t)(b0 + b) * NC + c) * DMODEL + d];
        S[b][0] = h.x; S[b][1] = h.y; S[b][2] = h.z; S[b][3] = h.w;
    }

    const size_t base = ((size_t)b0 * SEQ + (size_t)c * CHUNK) * DMODEL + d;
    const float* xbase = x + base;
    float*       ybase = y + base;

    float4 E1 = make_float4(0.f, 0.f, 0.f, 0.f);
    if (c > 0) E1 = computeE1(c, T1, T2, T3);
    float4 in0 = cv;

    #pragma unroll
    for (int r0 = 0; r0 < CHUNK; r0++) {
        if (r0 > 0) in0 = f4add(in0, cv);

        float xv[BPB];
        #pragma unroll
        for (int b = 0; b < BPB; b++)
            xv[b] = __ldg(xbase + ((size_t)b * SEQ + r0) * DMODEL);

        float4 cum = (c == 0) ? in0 : f4add(E1, in0);
        Fac f = factors_from_cum(cum);

        #pragma unroll
        for (int b = 0; b < BPB; b++) {
            float bur0 = br0 * xv[b], bui0 = bi0 * xv[b];
            float bur1 = br1 * xv[b], bui1 = bi1 * xv[b];
            S[b][0] = fmaf(f.dnr0, bur0, fmaf(-f.dni0, bui0, S[b][0]));
            S[b][1] = fmaf(f.dnr0, bui0, fmaf( f.dni0, bur0, S[b][1]));
            S[b][2] = fmaf(f.dnr1, bur1, fmaf(-f.dni1, bui1, S[b][2]));
            S[b][3] = fmaf(f.dnr1, bui1, fmaf( f.dni1, bur1, S[b][3]));

            // rescale: h = ec (.) S   (inclusive — after adding term t)
            float h0r = f.ecr0 * S[b][0] - f.eci0 * S[b][1];
            float h0i = f.ecr0 * S[b][1] + f.eci0 * S[b][0];
            float h1r = f.ecr1 * S[b][2] - f.eci1 * S[b][3];
            float h1i = f.ecr1 * S[b][3] + f.eci1 * S[b][2];

            float yv = fmaf(dd, xv[b],
                       fmaf(cr0, h0r, fmaf(-ci0, h0i,
                       fmaf(cr1, h1r, -ci1 * h1i))));
            __stcs(ybase + ((size_t)b * SEQ + r0) * DMODEL, yv);
        }
    }
}

// ---------------------------------------------------------------------------
extern "C" void kernel_launch(void* const* d_in, const int* in_sizes, int n_in,
                              void* d_out, int out_size)
{
    (void)in_sizes; (void)n_in; (void)out_size;
    const float* x   = (const float*)d_in[0];
    const float* lam = (const float*)d_in[1];
    const float* aph = (const float*)d_in[2];
    const float* Br  = (const float*)d_in[3];
    const float* Bi  = (const float*)d_in[4];
    const float* Cr  = (const float*)d_in[5];
    const float* Ci  = (const float*)d_in[6];
    const float* Dd  = (const float*)d_in[7];
    float* y = (float*)d_out;

    dim3 grid(NC, NBSPL);
    k_partial<<<grid, DMODEL>>>(x, aph, lam, Br, Bi);
    k_scan<<<(BATCH * DMODEL + 255) / 256, 256>>>();
    k_output<<<grid, DMODEL>>>(x, aph, lam, Br, Bi, Cr, Ci, Dd, y);
}

// round 12
// speedup vs baseline: 1.1561x; 1.1561x over previous
#include <cuda_runtime.h>
#include <cuda_bf16.h>
#include <math.h>

// Problem constants
#define BATCH   8
#define SEQ     8192
#define DMODEL  256
#define NC      512          // chunks along T
#define CHUNK   (SEQ / NC)   // 16  (== scan base block -> one E1 per chunk)
#define NBSPL   2            // batch splits across gridDim.y
#define BPB     (BATCH / NBSPL)  // 4 batches per block

// Scratch (__device__ globals; no cudaMalloc allowed):
// g_P : raw chunk-local complex sums; g_Hin: exclusive chunk prefix. 16.8 MB ea.
// Layout [(b*NC + c)*DMODEL + d] as float4 = (s0r, s0i, s1r, s1i).
__device__ float4 g_P  [BATCH * NC * DMODEL];
__device__ float4 g_Hin[BATCH * NC * DMODEL];

// ---------------------------------------------------------------------------
// Bit-exact emulation of XLA ReduceWindowRewriter's blocked-rescan cumsum of a
// CONSTANT c (base_length = 16), vectorized over 4 lanes
// (phase0, phase1, mag0, mag1). DO NOT TOUCH — this is the bit-critical part.
// ---------------------------------------------------------------------------
__device__ __forceinline__ float4 f4add(float4 a, float4 b) {
    return make_float4(a.x + b.x, a.y + b.y, a.z + b.z, a.w + b.w);
}

__device__ __forceinline__ float4 seqm(float4 v, int m) {   // m >= 1
    float4 a = v;
    for (int k = 1; k < m; k++) a = f4add(a, v);
    return a;
}

__device__ __forceinline__ float4 computeE1(int q, float4 T1, float4 T2, float4 T3) {
    // inclusive scan of constant T1 at q terms (1 <= q <= 511)
    int j  = q - 1, r1 = j & 15, q1 = j >> 4;        // q1 in [0,31]
    float4 in1 = seqm(T1, r1 + 1);
    if (q1 == 0) return in1;
    int j2 = q1 - 1, r2 = j2 & 15, q2 = j2 >> 4;     // q2 in {0,1}
    float4 in2 = seqm(T2, r2 + 1);
    float4 E2  = q2 ? f4add(T3, in2) : in2;
    return f4add(E2, in1);
}

// ---------------------------------------------------------------------------
// Branch-free sin/cos for x in [0, ~7e4): 3-term FMA Cody-Waite reduction
// mod pi/2, MUFU sin/cos on the reduced arg, quadrant fixup via selects.
// Function-VALUE error ~5e-7 abs — only the argument is bit-critical, and the
// argument is the exact fp32 cumsum value.
// ---------------------------------------------------------------------------
__device__ __forceinline__ void fast_sincos(float x, float& s, float& c) {
    float kf = rintf(x * 0.636619772f);          // x * 2/pi
    int   q  = (int)kf;
    float r  = fmaf(kf, -1.57079601e+00f, x);
    r        = fmaf(kf, -3.13916474e-07f, r);
    r        = fmaf(kf, -5.39030253e-15f, r);
    float sr = __sinf(r);
    float cr = __cosf(r);
    bool sw  = (q & 1);
    float ss = sw ? cr : sr;
    float cc = sw ? sr : cr;
    s = (q & 2)       ? -ss : ss;
    c = ((q + 1) & 2) ? -cc : cc;
}

// ---------------------------------------------------------------------------
// K1: chunk-local raw sums S = sum_t (dn_t ⊙ B) * x_t  (x real, so the
// coefficient product W = dn⊙B is folded once per (d,t): 4 FMA per batch).
// grid = (NC, NBSPL), block = DMODEL.
// ---------------------------------------------------------------------------
__global__ __launch_bounds__(DMODEL, 3) void k_partial(
    const float* __restrict__ x,
    const float* __restrict__ aph, const float* __restrict__ lam,
    const float* __restrict__ Br,  const float* __restrict__ Bi)
{
    const int d  = threadIdx.x;
    const int c  = blockIdx.x;
    const int b0 = blockIdx.y * BPB;

    const float4 cv = make_float4(aph[2 * d + 0], aph[2 * d + 1],
                                  lam[2 * d + 0], lam[2 * d + 1]);
    const float4 T1 = seqm(cv, 16);
    const float4 T2 = seqm(T1, 16);
    const float4 T3 = seqm(T2, 16);

    const float br0 = Br[2 * d + 0], br1 = Br[2 * d + 1];
    const float bi0 = Bi[2 * d + 0], bi1 = Bi[2 * d + 1];

    float S[BPB][4];
    #pragma unroll
    for (int b = 0; b < BPB; b++)
        S[b][0] = S[b][1] = S[b][2] = S[b][3] = 0.f;

    const float* xbase = x + ((size_t)b0 * SEQ + (size_t)c * CHUNK) * DMODEL + d;

    // exactly one 16-step scan block per chunk (q0 == c)
    float4 E1 = make_float4(0.f, 0.f, 0.f, 0.f);
    if (c > 0) E1 = computeE1(c, T1, T2, T3);
    float4 in0 = cv;

    #pragma unroll
    for (int r0 = 0; r0 < CHUNK; r0++) {
        if (r0 > 0) in0 = f4add(in0, cv);

        float xv[BPB];
        #pragma unroll
        for (int b = 0; b < BPB; b++)
            xv[b] = __ldg(xbase + ((size_t)b * SEQ + r0) * DMODEL);

        float4 cum = (c == 0) ? in0 : f4add(E1, in0);

        float sn0, cs0, sn1, cs1;
        fast_sincos(cum.x, sn0, cs0);
        fast_sincos(cum.y, sn1, cs1);
        float en0 = __expf(-cum.z), en1 = __expf(-cum.w);

        // W = dn ⊙ B,  dn = en*(cs, -sn)
        float Wr0 = en0 * fmaf(br0, cs0,  bi0 * sn0);
        float Wi0 = en0 * fmaf(bi0, cs0, -br0 * sn0);
        float Wr1 = en1 * fmaf(br1, cs1,  bi1 * sn1);
        float Wi1 = en1 * fmaf(bi1, cs1, -br1 * sn1);

        #pragma unroll
        for (int b = 0; b < BPB; b++) {
            S[b][0] = fmaf(Wr0, xv[b], S[b][0]);
            S[b][1] = fmaf(Wi0, xv[b], S[b][1]);
            S[b][2] = fmaf(Wr1, xv[b], S[b][2]);
            S[b][3] = fmaf(Wi1, xv[b], S[b][3]);
        }
    }

    #pragma unroll
    for (int b = 0; b < BPB; b++)
        g_P[((size_t)(b0 + b) * NC + c) * DMODEL + d] =
            make_float4(S[b][0], S[b][1], S[b][2], S[b][3]);
}

// ---------------------------------------------------------------------------
// K2: exclusive prefix SUM over chunks (plain addition — sums are raw).
// 2048 threads spread as 64 blocks x 32 threads -> 64 SMs issue loads.
// __ldcs: g_P is read-once — evict-first, keep L2 for x (K3 re-reads it).
// ---------------------------------------------------------------------------
__global__ void k_scan() {
    int idx = blockIdx.x * blockDim.x + threadIdx.x;
    if (idx >= BATCH * DMODEL) return;
    int b = idx >> 8;
    int d = idx & (DMODEL - 1);

    float4 s = make_float4(0.f, 0.f, 0.f, 0.f);
    #pragma unroll 16
    for (int c = 0; c < NC; c++) {
        size_t k = ((size_t)b * NC + c) * DMODEL + d;
        g_Hin[k] = s;
        float4 p = __ldcs(&g_P[k]);
        s.x += p.x; s.y += p.y; s.z += p.z; s.w += p.w;
    }
}

// ---------------------------------------------------------------------------
// K3: redo local sums seeded with carry, emit y directly via folded output
// coefficients G = C ⊙ ec:  y = dd*x + Gr0*S0r - Gi0*S0i + Gr1*S1r - Gi1*S1i.
// (Identical math to rescale-then-project, reassociated — ulp-level only.)
// grid = (NC, NBSPL). 128-reg budget: no spills.
// ---------------------------------------------------------------------------
__global__ __launch_bounds__(DMODEL, 2) void k_output(
    const float* __restrict__ x,
    const float* __restrict__ aph, const float* __restrict__ lam,
    const float* __restrict__ Br,  const float* __restrict__ Bi,
    const float* __restrict__ Cr,  const float* __restrict__ Ci,
    const float* __restrict__ Dd,
    float* __restrict__ y)
{
    const int d  = threadIdx.x;
    const int c  = blockIdx.x;
    const int b0 = blockIdx.y * BPB;

    const float4 cv = make_float4(aph[2 * d + 0], aph[2 * d + 1],
                                  lam[2 * d + 0], lam[2 * d + 1]);
    const float4 T1 = seqm(cv, 16);
    const float4 T2 = seqm(T1, 16);
    const float4 T3 = seqm(T2, 16);

    const float br0 = Br[2 * d + 0], br1 = Br[2 * d + 1];
    const float bi0 = Bi[2 * d + 0], bi1 = Bi[2 * d + 1];
    const float cr0 = Cr[2 * d + 0], cr1 = Cr[2 * d + 1];
    const float ci0 = Ci[2 * d + 0], ci1 = Ci[2 * d + 1];
    const float dd  = Dd[d];

    float S[BPB][4];
    #pragma unroll
    for (int b = 0; b < BPB; b++) {
        float4 h = g_Hin[((size_t)(b0 + b) * NC + c) * DMODEL + d];
        S[b][0] = h.x; S[b][1] = h.y; S[b][2] = h.z; S[b][3] = h.w;
    }

    const size_t base = ((size_t)b0 * SEQ + (size_t)c * CHUNK) * DMODEL + d;
    const float* xbase = x + base;
    float*       ybase = y + base;

    float4 E1 = make_float4(0.f, 0.f, 0.f, 0.f);
    if (c > 0) E1 = computeE1(c, T1, T2, T3);
    float4 in0 = cv;

    #pragma unroll
    for (int r0 = 0; r0 < CHUNK; r0++) {
        if (r0 > 0) in0 = f4add(in0, cv);

        float xv[BPB];
        #pragma unroll
        for (int b = 0; b < BPB; b++)
            xv[b] = __ldg(xbase + ((size_t)b * SEQ + r0) * DMODEL);

        float4 cum = (c == 0) ? in0 : f4add(E1, in0);

        float sn0, cs0, sn1, cs1;
        fast_sincos(cum.x, sn0, cs0);
        fast_sincos(cum.y, sn1, cs1);
        float en0 = __expf(-cum.z), ec0 = __expf(cum.z);
        float en1 = __expf(-cum.w), ec1 = __expf(cum.w);

        // W = dn ⊙ B (descale+input),  G = C ⊙ ec (rescale+output)
        float Wr0 = en0 * fmaf(br0, cs0,  bi0 * sn0);
        float Wi0 = en0 * fmaf(bi0, cs0, -br0 * sn0);
        float Wr1 = en1 * fmaf(br1, cs1,  bi1 * sn1);
        float Wi1 = en1 * fmaf(bi1, cs1, -br1 * sn1);
        float Gr0 = ec0 * fmaf(cr0, cs0, -ci0 * sn0);
        float Gi0 = ec0 * fmaf(cr0, sn0,  ci0 * cs0);
        float Gr1 = ec1 * fmaf(cr1, cs1, -ci1 * sn1);
        float Gi1 = ec1 * fmaf(cr1, sn1,  ci1 * cs1);

        #pragma unroll
        for (int b = 0; b < BPB; b++) {
            S[b][0] = fmaf(Wr0, xv[b], S[b][0]);
            S[b][1] = fmaf(Wi0, xv[b], S[b][1]);
            S[b][2] = fmaf(Wr1, xv[b], S[b][2]);
            S[b][3] = fmaf(Wi1, xv[b], S[b][3]);

            float yv = fmaf(dd, xv[b],
                       fmaf(Gr0, S[b][0], fmaf(-Gi0, S[b][1],
                       fmaf(Gr1, S[b][2], -Gi1 * S[b][3]))));
            __stcs(ybase + ((size_t)b * SEQ + r0) * DMODEL, yv);
        }
    }
}

// ---------------------------------------------------------------------------
extern "C" void kernel_launch(void* const* d_in, const int* in_sizes, int n_in,
                              void* d_out, int out_size)
{
    (void)in_sizes; (void)n_in; (void)out_size;
    const float* x   = (const float*)d_in[0];
    const float* lam = (const float*)d_in[1];
    const float* aph = (const float*)d_in[2];
    const float* Br  = (const float*)d_in[3];
    const float* Bi  = (const float*)d_in[4];
    const float* Cr  = (const float*)d_in[5];
    const float* Ci  = (const float*)d_in[6];
    const float* Dd  = (const float*)d_in[7];
    float* y = (float*)d_out;

    dim3 grid(NC, NBSPL);
    k_partial<<<grid, DMODEL>>>(x, aph, lam, Br, Bi);
    k_scan<<<64, 32>>>();
    k_output<<<grid, DMODEL>>>(x, aph, lam, Br, Bi, Cr, Ci, Dd, y);
}

// round 13
// speedup vs baseline: 1.3799x; 1.1936x over previous
#include <cuda_runtime.h>
#include <cuda_bf16.h>
#include <math.h>

// Problem constants
#define BATCH   8
#define SEQ     8192
#define DMODEL  256
#define NC      512          // chunks along T
#define CHUNK   (SEQ / NC)   // 16  (== scan base block -> one E1 per chunk)
#define NBSPL   2            // batch splits across gridDim.y
#define BPB     (BATCH / NBSPL)  // 4 batches per block

// Scratch (__device__ globals; no cudaMalloc allowed):
// g_P : raw chunk-local complex sums; g_Hin: exclusive chunk prefix. 16.8 MB ea.
// g_E1: per-(chunk,d) outer scan prefix (the bit-exact cumsum block offset). 2 MB.
__device__ float4 g_P  [BATCH * NC * DMODEL];
__device__ float4 g_Hin[BATCH * NC * DMODEL];
__device__ float4 g_E1 [NC * DMODEL];

// ---------------------------------------------------------------------------
// Bit-exact emulation of XLA ReduceWindowRewriter's blocked-rescan cumsum of a
// CONSTANT c (base_length = 16), vectorized over 4 lanes
// (phase0, phase1, mag0, mag1). DO NOT TOUCH — this is the bit-critical part.
// ---------------------------------------------------------------------------
__device__ __forceinline__ float4 f4add(float4 a, float4 b) {
    return make_float4(a.x + b.x, a.y + b.y, a.z + b.z, a.w + b.w);
}

__device__ __forceinline__ float4 seqm(float4 v, int m) {   // m >= 1
    float4 a = v;
    for (int k = 1; k < m; k++) a = f4add(a, v);
    return a;
}

__device__ __forceinline__ float4 computeE1(int q, float4 T1, float4 T2, float4 T3) {
    // inclusive scan of constant T1 at q terms (1 <= q <= 511)
    int j  = q - 1, r1 = j & 15, q1 = j >> 4;        // q1 in [0,31]
    float4 in1 = seqm(T1, r1 + 1);
    if (q1 == 0) return in1;
    int j2 = q1 - 1, r2 = j2 & 15, q2 = j2 >> 4;     // q2 in {0,1}
    float4 in2 = seqm(T2, r2 + 1);
    float4 E2  = q2 ? f4add(T3, in2) : in2;
    return f4add(E2, in1);
}

// ---------------------------------------------------------------------------
// Branch-free sin/cos for x in [0, ~7e4): 3-term FMA Cody-Waite reduction
// mod pi/2, MUFU sin/cos on the reduced arg, quadrant fixup via selects.
// Function-VALUE error ~5e-7 abs — only the argument is bit-critical, and the
// argument is the exact fp32 cumsum value.
// ---------------------------------------------------------------------------
__device__ __forceinline__ void fast_sincos(float x, float& s, float& c) {
    float kf = rintf(x * 0.636619772f);          // x * 2/pi
    int   q  = (int)kf;
    float r  = fmaf(kf, -1.57079601e+00f, x);
    r        = fmaf(kf, -3.13916474e-07f, r);
    r        = fmaf(kf, -5.39030253e-15f, r);
    float sr = __sinf(r);
    float cr = __cosf(r);
    bool sw  = (q & 1);
    float ss = sw ? cr : sr;
    float cc = sw ? sr : cr;
    s = (q & 2)       ? -ss : ss;
    c = ((q + 1) & 2) ? -cc : cc;
}

// ---------------------------------------------------------------------------
// K0: build the E1 table once (batch-independent, chunk-level scan prefixes).
// grid = NC/16 blocks, DMODEL threads. E1[0] = 0 (fl(0+v)=v keeps bit-exact).
// ---------------------------------------------------------------------------
__global__ __launch_bounds__(DMODEL) void k_e1(
    const float* __restrict__ aph, const float* __restrict__ lam)
{
    const int d  = threadIdx.x;
    const int cg = blockIdx.x;                       // chunk group of 16

    const float4 cv = make_float4(aph[2 * d + 0], aph[2 * d + 1],
                                  lam[2 * d + 0], lam[2 * d + 1]);
    const float4 T1 = seqm(cv, 16);
    const float4 T2 = seqm(T1, 16);
    const float4 T3 = seqm(T2, 16);

    for (int i = 0; i < 16; i++) {
        int c = cg * 16 + i;
        float4 e = (c == 0) ? make_float4(0.f, 0.f, 0.f, 0.f)
                            : computeE1(c, T1, T2, T3);
        g_E1[(size_t)c * DMODEL + d] = e;
    }
}

// ---------------------------------------------------------------------------
// K1: chunk-local raw sums S = sum_t (dn_t ⊙ B) * x_t  (W = dn⊙B folded).
// grid = (NC, NBSPL), block = DMODEL. Prologue = a few loads, no add-chains.
// ---------------------------------------------------------------------------
__global__ __launch_bounds__(DMODEL, 3) void k_partial(
    const float* __restrict__ x,
    const float* __restrict__ aph, const float* __restrict__ lam,
    const float* __restrict__ Br,  const float* __restrict__ Bi)
{
    const int d  = threadIdx.x;
    const int c  = blockIdx.x;
    const int b0 = blockIdx.y * BPB;

    const float4 cv = make_float4(aph[2 * d + 0], aph[2 * d + 1],
                                  lam[2 * d + 0], lam[2 * d + 1]);
    const float4 E1 = g_E1[(size_t)c * DMODEL + d];

    const float br0 = Br[2 * d + 0], br1 = Br[2 * d + 1];
    const float bi0 = Bi[2 * d + 0], bi1 = Bi[2 * d + 1];

    float S[BPB][4];
    #pragma unroll
    for (int b = 0; b < BPB; b++)
        S[b][0] = S[b][1] = S[b][2] = S[b][3] = 0.f;

    const float* xbase = x + ((size_t)b0 * SEQ + (size_t)c * CHUNK) * DMODEL + d;

    float4 in0 = cv;
    #pragma unroll
    for (int r0 = 0; r0 < CHUNK; r0++) {
        if (r0 > 0) in0 = f4add(in0, cv);

        float xv[BPB];
        #pragma unroll
        for (int b = 0; b < BPB; b++)
            xv[b] = __ldg(xbase + ((size_t)b * SEQ + r0) * DMODEL);

        float4 cum = f4add(E1, in0);     // E1[0]=0 -> exact for c==0

        float sn0, cs0, sn1, cs1;
        fast_sincos(cum.x, sn0, cs0);
        fast_sincos(cum.y, sn1, cs1);
        float en0 = __expf(-cum.z), en1 = __expf(-cum.w);

        // W = dn ⊙ B,  dn = en*(cs, -sn)
        float Wr0 = en0 * fmaf(br0, cs0,  bi0 * sn0);
        float Wi0 = en0 * fmaf(bi0, cs0, -br0 * sn0);
        float Wr1 = en1 * fmaf(br1, cs1,  bi1 * sn1);
        float Wi1 = en1 * fmaf(bi1, cs1, -br1 * sn1);

        #pragma unroll
        for (int b = 0; b < BPB; b++) {
            S[b][0] = fmaf(Wr0, xv[b], S[b][0]);
            S[b][1] = fmaf(Wi0, xv[b], S[b][1]);
            S[b][2] = fmaf(Wr1, xv[b], S[b][2]);
            S[b][3] = fmaf(Wi1, xv[b], S[b][3]);
        }
    }

    #pragma unroll
    for (int b = 0; b < BPB; b++)
        g_P[((size_t)(b0 + b) * NC + c) * DMODEL + d] =
            make_float4(S[b][0], S[b][1], S[b][2], S[b][3]);
}

// ---------------------------------------------------------------------------
// K2: exclusive prefix SUM over chunks (plain addition — sums are raw).
// 2048 threads spread as 64 blocks x 32 threads -> 64 SMs issue loads.
// ---------------------------------------------------------------------------
__global__ void k_scan() {
    int idx = blockIdx.x * blockDim.x + threadIdx.x;
    if (idx >= BATCH * DMODEL) return;
    int b = idx >> 8;
    int d = idx & (DMODEL - 1);

    float4 s = make_float4(0.f, 0.f, 0.f, 0.f);
    #pragma unroll 16
    for (int c = 0; c < NC; c++) {
        size_t k = ((size_t)b * NC + c) * DMODEL + d;
        g_Hin[k] = s;
        float4 p = __ldcs(&g_P[k]);
        s.x += p.x; s.y += p.y; s.z += p.z; s.w += p.w;
    }
}

// ---------------------------------------------------------------------------
// K3: redo local sums seeded with carry, emit y via folded output coeffs
// G = C ⊙ ec:  y = dd*x + Gr0*S0r - Gi0*S0i + Gr1*S1r - Gi1*S1i.
// Same shape as k_partial (same bounds, E1 from table -> small live set).
// ---------------------------------------------------------------------------
__global__ __launch_bounds__(DMODEL, 3) void k_output(
    const float* __restrict__ x,
    const float* __restrict__ aph, const float* __restrict__ lam,
    const float* __restrict__ Br,  const float* __restrict__ Bi,
    const float* __restrict__ Cr,  const float* __restrict__ Ci,
    const float* __restrict__ Dd,
    float* __restrict__ y)
{
    const int d  = threadIdx.x;
    const int c  = blockIdx.x;
    const int b0 = blockIdx.y * BPB;

    const float4 cv = make_float4(aph[2 * d + 0], aph[2 * d + 1],
                                  lam[2 * d + 0], lam[2 * d + 1]);
    const float4 E1 = g_E1[(size_t)c * DMODEL + d];

    const float br0 = Br[2 * d + 0], br1 = Br[2 * d + 1];
    const float bi0 = Bi[2 * d + 0], bi1 = Bi[2 * d + 1];
    const float cr0 = Cr[2 * d + 0], cr1 = Cr[2 * d + 1];
    const float ci0 = Ci[2 * d + 0], ci1 = Ci[2 * d + 1];
    const float dd  = Dd[d];

    float S[BPB][4];
    #pragma unroll
    for (int b = 0; b < BPB; b++) {
        float4 h = g_Hin[((size_t)(b0 + b) * NC + c) * DMODEL + d];
        S[b][0] = h.x; S[b][1] = h.y; S[b][2] = h.z; S[b][3] = h.w;
    }

    const size_t base = ((size_t)b0 * SEQ + (size_t)c * CHUNK) * DMODEL + d;
    const float* xbase = x + base;
    float*       ybase = y + base;

    float4 in0 = cv;
    #pragma unroll
    for (int r0 = 0; r0 < CHUNK; r0++) {
        if (r0 > 0) in0 = f4add(in0, cv);

        float xv[BPB];
        #pragma unroll
        for (int b = 0; b < BPB; b++)
            xv[b] = __ldg(xbase + ((size_t)b * SEQ + r0) * DMODEL);

        float4 cum = f4add(E1, in0);     // E1[0]=0 -> exact for c==0

        float sn0, cs0, sn1, cs1;
        fast_sincos(cum.x, sn0, cs0);
        fast_sincos(cum.y, sn1, cs1);
        float en0 = __expf(-cum.z), ec0 = __expf(cum.z);
        float en1 = __expf(-cum.w), ec1 = __expf(cum.w);

        // W = dn ⊙ B (descale+input),  G = C ⊙ ec (rescale+output)
        float Wr0 = en0 * fmaf(br0, cs0,  bi0 * sn0);
        float Wi0 = en0 * fmaf(bi0, cs0, -br0 * sn0);
        float Wr1 = en1 * fmaf(br1, cs1,  bi1 * sn1);
        float Wi1 = en1 * fmaf(bi1, cs1, -br1 * sn1);
        float Gr0 = ec0 * fmaf(cr0, cs0, -ci0 * sn0);
        float Gi0 = ec0 * fmaf(cr0, sn0,  ci0 * cs0);
        float Gr1 = ec1 * fmaf(cr1, cs1, -ci1 * sn1);
        float Gi1 = ec1 * fmaf(cr1, sn1,  ci1 * cs1);

        #pragma unroll
        for (int b = 0; b < BPB; b++) {
            S[b][0] = fmaf(Wr0, xv[b], S[b][0]);
            S[b][1] = fmaf(Wi0, xv[b], S[b][1]);
            S[b][2] = fmaf(Wr1, xv[b], S[b][2]);
            S[b][3] = fmaf(Wi1, xv[b], S[b][3]);

            float yv = fmaf(dd, xv[b],
                       fmaf(Gr0, S[b][0], fmaf(-Gi0, S[b][1],
                       fmaf(Gr1, S[b][2], -Gi1 * S[b][3]))));
            __stcs(ybase + ((size_t)b * SEQ + r0) * DMODEL, yv);
        }
    }
}

// ---------------------------------------------------------------------------
extern "C" void kernel_launch(void* const* d_in, const int* in_sizes, int n_in,
                              void* d_out, int out_size)
{
    (void)in_sizes; (void)n_in; (void)out_size;
    const float* x   = (const float*)d_in[0];
    const float* lam = (const float*)d_in[1];
    const float* aph = (const float*)d_in[2];
    const float* Br  = (const float*)d_in[3];
    const float* Bi  = (const float*)d_in[4];
    const float* Cr  = (const float*)d_in[5];
    const float* Ci  = (const float*)d_in[6];
    const float* Dd  = (const float*)d_in[7];
    float* y = (float*)d_out;

    k_e1<<<NC / 16, DMODEL>>>(aph, lam);
    dim3 grid(NC, NBSPL);
    k_partial<<<grid, DMODEL>>>(x, aph, lam, Br, Bi);
    k_scan<<<64, 32>>>();
    k_output<<<grid, DMODEL>>>(x, aph, lam, Br, Bi, Cr, Ci, Dd, y);
}

// round 15
// speedup vs baseline: 3.2198x; 2.3333x over previous
#include <cuda_runtime.h>
#include <cuda_bf16.h>
#include <math.h>

// Problem constants
#define BATCH   8
#define SEQ     8192
#define DMODEL  256
#define NC      512          // chunks along T
#define CHUNK   (SEQ / NC)   // 16  (== scan base block -> one E1 per chunk)
#define NBSPL   2            // batch splits across gridDim.y
#define BPB     (BATCH / NBSPL)  // 4 batches per block
#define NSEG    32           // segments for the hierarchical chunk scan
#define CPS     (NC / NSEG)  // 16 chunks per segment

// Scratch (__device__ globals; no cudaMalloc allowed):
// g_P : raw chunk-local complex sums; g_Hin: per-chunk carry-in. 16.8 MB ea.
// g_E1: per-(chunk,d) outer scan prefix (bit-exact cumsum block offset). 2 MB.
// g_T : per-(b,seg,d) segment totals -> exclusive prefixes. 1 MB.
__device__ float4 g_P  [BATCH * NC * DMODEL];
__device__ float4 g_Hin[BATCH * NC * DMODEL];
__device__ float4 g_E1 [NC * DMODEL];
__device__ float4 g_T  [BATCH * NSEG * DMODEL];

// ---------------------------------------------------------------------------
// Bit-exact emulation of XLA ReduceWindowRewriter's blocked-rescan cumsum of a
// CONSTANT c (base_length = 16), vectorized over 4 lanes
// (phase0, phase1, mag0, mag1). DO NOT TOUCH — this is the bit-critical part.
// ---------------------------------------------------------------------------
__device__ __forceinline__ float4 f4add(float4 a, float4 b) {
    return make_float4(a.x + b.x, a.y + b.y, a.z + b.z, a.w + b.w);
}

__device__ __forceinline__ float4 seqm(float4 v, int m) {   // m >= 1
    float4 a = v;
    for (int k = 1; k < m; k++) a = f4add(a, v);
    return a;
}

__device__ __forceinline__ float4 computeE1(int q, float4 T1, float4 T2, float4 T3) {
    // inclusive scan of constant T1 at q terms (1 <= q <= 511)
    int j  = q - 1, r1 = j & 15, q1 = j >> 4;        // q1 in [0,31]
    float4 in1 = seqm(T1, r1 + 1);
    if (q1 == 0) return in1;
    int j2 = q1 - 1, r2 = j2 & 15, q2 = j2 >> 4;     // q2 in {0,1}
    float4 in2 = seqm(T2, r2 + 1);
    float4 E2  = q2 ? f4add(T3, in2) : in2;
    return f4add(E2, in1);
}

// ---------------------------------------------------------------------------
// Branch-free sin/cos: 3-term FMA Cody-Waite reduction mod pi/2, MUFU on the
// reduced arg, quadrant fixup via selects. Value error ~5e-7 abs — only the
// argument is bit-critical, and the argument is the exact fp32 cumsum value.
// ---------------------------------------------------------------------------
__device__ __forceinline__ void fast_sincos(float x, float& s, float& c) {
    float kf = rintf(x * 0.636619772f);          // x * 2/pi
    int   q  = (int)kf;
    float r  = fmaf(kf, -1.57079601e+00f, x);
    r        = fmaf(kf, -3.13916474e-07f, r);
    r        = fmaf(kf, -5.39030253e-15f, r);
    float sr = __sinf(r);
    float cr = __cosf(r);
    bool sw  = (q & 1);
    float ss = sw ? cr : sr;
    float cc = sw ? sr : cr;
    s = (q & 2)       ? -ss : ss;
    c = ((q + 1) & 2) ? -cc : cc;
}

// ---------------------------------------------------------------------------
// K0: build the E1 table once (batch-independent, chunk-level scan prefixes).
// grid = NC/16 blocks, DMODEL threads. E1[0] = 0 (fl(0+v)=v keeps bit-exact).
// ---------------------------------------------------------------------------
__global__ __launch_bounds__(DMODEL) void k_e1(
    const float* __restrict__ aph, const float* __restrict__ lam)
{
    const int d  = threadIdx.x;
    const int cg = blockIdx.x;                       // chunk group of 16

    const float4 cv = make_float4(aph[2 * d + 0], aph[2 * d + 1],
                                  lam[2 * d + 0], lam[2 * d + 1]);
    const float4 T1 = seqm(cv, 16);
    const float4 T2 = seqm(T1, 16);
    const float4 T3 = seqm(T2, 16);

    for (int i = 0; i < 16; i++) {
        int c = cg * 16 + i;
        float4 e = (c == 0) ? make_float4(0.f, 0.f, 0.f, 0.f)
                            : computeE1(c, T1, T2, T3);
        g_E1[(size_t)c * DMODEL + d] = e;
    }
}

// ---------------------------------------------------------------------------
// K1: chunk-local raw sums S = sum_t (dn_t ⊙ B) * x_t  (W = dn⊙B folded).
// grid = (NC, NBSPL), block = DMODEL.
// ---------------------------------------------------------------------------
__global__ __launch_bounds__(DMODEL, 3) void k_partial(
    const float* __restrict__ x,
    const float* __restrict__ aph, const float* __restrict__ lam,
    const float* __restrict__ Br,  const float* __restrict__ Bi)
{
    const int d  = threadIdx.x;
    const int c  = blockIdx.x;
    const int b0 = blockIdx.y * BPB;

    const float4 cv = make_float4(aph[2 * d + 0], aph[2 * d + 1],
                                  lam[2 * d + 0], lam[2 * d + 1]);
    const float4 E1 = g_E1[(size_t)c * DMODEL + d];

    const float br0 = Br[2 * d + 0], br1 = Br[2 * d + 1];
    const float bi0 = Bi[2 * d + 0], bi1 = Bi[2 * d + 1];

    float S[BPB][4];
    #pragma unroll
    for (int b = 0; b < BPB; b++)
        S[b][0] = S[b][1] = S[b][2] = S[b][3] = 0.f;

    const float* xbase = x + ((size_t)b0 * SEQ + (size_t)c * CHUNK) * DMODEL + d;

    float4 in0 = cv;
    #pragma unroll
    for (int r0 = 0; r0 < CHUNK; r0++) {
        if (r0 > 0) in0 = f4add(in0, cv);

        float xv[BPB];
        #pragma unroll
        for (int b = 0; b < BPB; b++)
            xv[b] = __ldg(xbase + ((size_t)b * SEQ + r0) * DMODEL);

        float4 cum = f4add(E1, in0);     // E1[0]=0 -> exact for c==0

        float sn0, cs0, sn1, cs1;
        fast_sincos(cum.x, sn0, cs0);
        fast_sincos(cum.y, sn1, cs1);
        float en0 = __expf(-cum.z), en1 = __expf(-cum.w);

        float Wr0 = en0 * fmaf(br0, cs0,  bi0 * sn0);
        float Wi0 = en0 * fmaf(bi0, cs0, -br0 * sn0);
        float Wr1 = en1 * fmaf(br1, cs1,  bi1 * sn1);
        float Wi1 = en1 * fmaf(bi1, cs1, -br1 * sn1);

        #pragma unroll
        for (int b = 0; b < BPB; b++) {
            S[b][0] = fmaf(Wr0, xv[b], S[b][0]);
            S[b][1] = fmaf(Wi0, xv[b], S[b][1]);
            S[b][2] = fmaf(Wr1, xv[b], S[b][2]);
            S[b][3] = fmaf(Wi1, xv[b], S[b][3]);
        }
    }

    #pragma unroll
    for (int b = 0; b < BPB; b++)
        g_P[((size_t)(b0 + b) * NC + c) * DMODEL + d] =
            make_float4(S[b][0], S[b][1], S[b][2], S[b][3]);
}

// ---------------------------------------------------------------------------
// K2a: segment totals. grid = (NSEG, BATCH) x DMODEL threads.
// Each thread sums its segment's 16 chunk partials.
// ---------------------------------------------------------------------------
__global__ __launch_bounds__(DMODEL) void k_seg_sum() {
    const int d   = threadIdx.x;
    const int seg = blockIdx.x;
    const int b   = blockIdx.y;

    const float4* p = g_P + ((size_t)b * NC + (size_t)seg * CPS) * DMODEL + d;
    float4 s = make_float4(0.f, 0.f, 0.f, 0.f);
    #pragma unroll
    for (int i = 0; i < CPS; i++) {
        float4 v = p[(size_t)i * DMODEL];
        s.x += v.x; s.y += v.y; s.z += v.z; s.w += v.w;
    }
    g_T[((size_t)b * NSEG + seg) * DMODEL + d] = s;
}

// ---------------------------------------------------------------------------
// K2b: in-place exclusive scan of the 32 segment totals per (b,d).
// 2048 threads; 32 short iterations.
// ---------------------------------------------------------------------------
__global__ void k_seg_scan() {
    int idx = blockIdx.x * blockDim.x + threadIdx.x;
    if (idx >= BATCH * DMODEL) return;
    int b = idx >> 8;
    int d = idx & (DMODEL - 1);

    float4 s = make_float4(0.f, 0.f, 0.f, 0.f);
    #pragma unroll
    for (int seg = 0; seg < NSEG; seg++) {
        size_t k = ((size_t)b * NSEG + seg) * DMODEL + d;
        float4 t = g_T[k];
        g_T[k] = s;
        s.x += t.x; s.y += t.y; s.z += t.z; s.w += t.w;
    }
}

// ---------------------------------------------------------------------------
// K2c: expand carries: per-chunk exclusive prefix within each segment,
// seeded by the segment's exclusive base. grid = (NSEG, BATCH) x DMODEL.
// ---------------------------------------------------------------------------
__global__ __launch_bounds__(DMODEL) void k_carry() {
    const int d   = threadIdx.x;
    const int seg = blockIdx.x;
    const int b   = blockIdx.y;

    float4 s = g_T[((size_t)b * NSEG + seg) * DMODEL + d];
    const size_t base = ((size_t)b * NC + (size_t)seg * CPS) * DMODEL + d;
    #pragma unroll
    for (int i = 0; i < CPS; i++) {
        size_t k = base + (size_t)i * DMODEL;
        g_Hin[k] = s;
        float4 p = g_P[k];
        s.x += p.x; s.y += p.y; s.z += p.z; s.w += p.w;
    }
}

// ---------------------------------------------------------------------------
// K3: redo local sums seeded with carry, emit y via folded output coeffs
// G = C ⊙ ec:  y = dd*x + Gr0*S0r - Gi0*S0i + Gr1*S1r - Gi1*S1i.
// ---------------------------------------------------------------------------
__global__ __launch_bounds__(DMODEL, 3) void k_output(
    const float* __restrict__ x,
    const float* __restrict__ aph, const float* __restrict__ lam,
    const float* __restrict__ Br,  const float* __restrict__ Bi,
    const float* __restrict__ Cr,  const float* __restrict__ Ci,
    const float* __restrict__ Dd,
    float* __restrict__ y)
{
    const int d  = threadIdx.x;
    const int c  = blockIdx.x;
    const int b0 = blockIdx.y * BPB;

    const float4 cv = make_float4(aph[2 * d + 0], aph[2 * d + 1],
                                  lam[2 * d + 0], lam[2 * d + 1]);
    const float4 E1 = g_E1[(size_t)c * DMODEL + d];

    const float br0 = Br[2 * d + 0], br1 = Br[2 * d + 1];
    const float bi0 = Bi[2 * d + 0], bi1 = Bi[2 * d + 1];
    const float cr0 = Cr[2 * d + 0], cr1 = Cr[2 * d + 1];
    const float ci0 = Ci[2 * d + 0], ci1 = Ci[2 * d + 1];
    const float dd  = Dd[d];

    float S[BPB][4];
    #pragma unroll
    for (int b = 0; b < BPB; b++) {
        float4 h = g_Hin[((size_t)(b0 + b) * NC + c) * DMODEL + d];
        S[b][0] = h.x; S[b][1] = h.y; S[b][2] = h.z; S[b][3] = h.w;
    }

    const size_t base = ((size_t)b0 * SEQ + (size_t)c * CHUNK) * DMODEL + d;
    const float* xbase = x + base;
    float*       ybase = y + base;

    float4 in0 = cv;
    #pragma unroll
    for (int r0 = 0; r0 < CHUNK; r0++) {
        if (r0 > 0) in0 = f4add(in0, cv);

        float xv[BPB];
        #pragma unroll
        for (int b = 0; b < BPB; b++)
            xv[b] = __ldg(xbase + ((size_t)b * SEQ + r0) * DMODEL);

        float4 cum = f4add(E1, in0);     // E1[0]=0 -> exact for c==0

        float sn0, cs0, sn1, cs1;
        fast_sincos(cum.x, sn0, cs0);
        fast_sincos(cum.y, sn1, cs1);
        float en0 = __expf(-cum.z), ec0 = __expf(cum.z);
        float en1 = __expf(-cum.w), ec1 = __expf(cum.w);

        float Wr0 = en0 * fmaf(br0, cs0,  bi0 * sn0);
        float Wi0 = en0 * fmaf(bi0, cs0, -br0 * sn0);
        float Wr1 = en1 * fmaf(br1, cs1,  bi1 * sn1);
        float Wi1 = en1 * fmaf(bi1, cs1, -br1 * sn1);
        float Gr0 = ec0 * fmaf(cr0, cs0, -ci0 * sn0);
        float Gi0 = ec0 * fmaf(cr0, sn0,  ci0 * cs0);
        float Gr1 = ec1 * fmaf(cr1, cs1, -ci1 * sn1);
        float Gi1 = ec1 * fmaf(cr1, sn1,  ci1 * cs1);

        #pragma unroll
        for (int b = 0; b < BPB; b++) {
            S[b][0] = fmaf(Wr0, xv[b], S[b][0]);
            S[b][1] = fmaf(Wi0, xv[b], S[b][1]);
            S[b][2] = fmaf(Wr1, xv[b], S[b][2]);
            S[b][3] = fmaf(Wi1, xv[b], S[b][3]);

            float yv = fmaf(dd, xv[b],
                       fmaf(Gr0, S[b][0], fmaf(-Gi0, S[b][1],
                       fmaf(Gr1, S[b][2], -Gi1 * S[b][3]))));
            __stcs(ybase + ((size_t)b * SEQ + r0) * DMODEL, yv);
        }
    }
}

// ---------------------------------------------------------------------------
extern "C" void kernel_launch(void* const* d_in, const int* in_sizes, int n_in,
                              void* d_out, int out_size)
{
    (void)in_sizes; (void)n_in; (void)out_size;
    const float* x   = (const float*)d_in[0];
    const float* lam = (const float*)d_in[1];
    const float* aph = (const float*)d_in[2];
    const float* Br  = (const float*)d_in[3];
    const float* Bi  = (const float*)d_in[4];
    const float* Cr  = (const float*)d_in[5];
    const float* Ci  = (const float*)d_in[6];
    const float* Dd  = (const float*)d_in[7];
    float* y = (float*)d_out;

    k_e1<<<NC / 16, DMODEL>>>(aph, lam);
    dim3 grid(NC, NBSPL);
    k_partial<<<grid, DMODEL>>>(x, aph, lam, Br, Bi);
    dim3 sgrid(NSEG, BATCH);
    k_seg_sum<<<sgrid, DMODEL>>>();
    k_seg_scan<<<8, 256>>>();
    k_carry<<<sgrid, DMODEL>>>();
    k_output<<<grid, DMODEL>>>(x, aph, lam, Br, Bi, Cr, Ci, Dd, y);
}